// round 2
// baseline (speedup 1.0000x reference)
#include <cuda_runtime.h>

#define BB 256
#define NN 1000
#define DD 128
#define HH 8
#define NEGV (-1e9f)

// ---- packed f32x2 helpers (sm_103a) ----
static __device__ __forceinline__ unsigned long long packdup(float a) {
    unsigned long long r; unsigned int u = __float_as_uint(a);
    asm("mov.b64 %0, {%1, %2};" : "=l"(r) : "r"(u), "r"(u));
    return r;
}
static __device__ __forceinline__ unsigned long long fma2(unsigned long long a,
                                                          unsigned long long b,
                                                          unsigned long long c) {
    unsigned long long d;
    asm("fma.rn.f32x2 %0, %1, %2, %3;" : "=l"(d) : "l"(a), "l"(b), "l"(c));
    return d;
}
static __device__ __forceinline__ unsigned long long add2(unsigned long long a,
                                                          unsigned long long b) {
    unsigned long long d;
    asm("add.rn.f32x2 %0, %1, %2;" : "=l"(d) : "l"(a), "l"(b));
    return d;
}
static __device__ __forceinline__ float2 unpack2(unsigned long long v) {
    unsigned int lo, hi;
    asm("mov.b64 {%0, %1}, %2;" : "=r"(lo), "=r"(hi) : "l"(v));
    return make_float2(__uint_as_float(lo), __uint_as_float(hi));
}

__global__ __launch_bounds__(256) void attn_fused_kernel(
    const float* __restrict__ emb,        // [B, N, D]
    const float* __restrict__ Wn,         // [D, 3D]
    const float* __restrict__ Wf,         // [D, D]
    const float* __restrict__ Ws,         // [2D, D]
    const float* __restrict__ Wo,         // [D, D]
    const int*   __restrict__ fidx,       // [B]
    const int*   __restrict__ lidx,       // [B]
    const int*   __restrict__ mask,       // [B, N] bool stored as int32
    float* __restrict__ out)              // [B, N]
{
    __shared__ __align__(16) float s_compat[HH * NN];   // 32000 B (attn / logits scratch)
    __shared__ __align__(16) float s_QT[DD * HH];       // qtilde [d][h], scale folded
    __shared__ __align__(16) float s_ebar[HH * DD];     // attn-weighted emb sums (also phase-0 scratch)
    __shared__ __align__(16) float s_mean[DD];
    __shared__ __align__(16) float s_q[DD];
    __shared__ __align__(16) float s_ef[DD];
    __shared__ __align__(16) float s_el[DD];
    __shared__ __align__(16) float s_heads[DD];
    __shared__ __align__(16) float s_gl[DD];
    __shared__ __align__(16) float s_gt[DD];
    __shared__ float s_red[16];

    const int b = blockIdx.x;
    const int t = threadIdx.x;
    const int lane = t & 31;
    const int warp = t >> 5;
    const float* embB = emb + (size_t)b * NN * DD;
    const int* mkB = mask + (size_t)b * NN;

    // ---------------- Phase 0: graph mean + first/last rows ----------------
    {
        int d = t & 127, g = t >> 7;
        float a0 = 0.f, a1 = 0.f;
        int n = g;
        for (; n + 2 < NN; n += 4) {
            a0 += embB[(size_t)n * DD + d];
            a1 += embB[(size_t)(n + 2) * DD + d];
        }
        if (n < NN) a0 += embB[(size_t)n * DD + d];
        s_ebar[g * DD + d] = a0 + a1;   // scratch (two half-sums per dim)
    }
    {
        int fi = fidx[b], li = lidx[b];
        if (t < DD) s_ef[t] = embB[(size_t)fi * DD + t];
        else        s_el[t - DD] = embB[(size_t)li * DD + (t - DD)];
    }
    __syncthreads();
    if (t < DD) s_mean[t] = (s_ebar[t] + s_ebar[DD + t]) * (1.0f / NN);
    __syncthreads();

    // ---------------- Phase 0b: q = fixed_ctx + step_ctx @ W_step ----------
    if (t < DD) {
        float acc = 0.f;
        for (int i = 0; i < DD; i++) acc += s_mean[i] * Wf[i * DD + t];
        for (int i = 0; i < DD; i++) acc += s_ef[i] * Ws[i * DD + t];
        for (int i = 0; i < DD; i++) acc += s_el[i] * Ws[(DD + i) * DD + t];
        s_q[t] = acc;
    }
    __syncthreads();

    // ------------- Phase 0c: qtilde[d][h] = 0.25 * W_K[d, h-slice] . q_h ---
    {
        int d = t >> 1;
        int h0 = (t & 1) * 4;
        #pragma unroll
        for (int h = h0; h < h0 + 4; h++) {
            const float* w = Wn + d * 384 + h * 16;
            const float* qq = s_q + h * 16;
            float acc = 0.f;
            #pragma unroll
            for (int k = 0; k < 16; k++) acc += w[k] * qq[k];
            s_QT[d * HH + h] = acc * 0.25f;   // fold 1/sqrt(dk)
        }
    }
    __syncthreads();

    // ---------------- Phase 1: compat[h][n] = emb[n] . qtilde[:,h] ---------
    for (int n = t; n < NN; n += 256) {
        const float4* e4 = (const float4*)(embB + (size_t)n * DD);
        unsigned long long accA[4] = {0ull, 0ull, 0ull, 0ull};
        unsigned long long accB[4] = {0ull, 0ull, 0ull, 0ull};
        #pragma unroll 4
        for (int j = 0; j < 32; j++) {
            float4 e = e4[j];
            const ulonglong2* qt = (const ulonglong2*)(s_QT + j * 32); // rows 4j..4j+3
            unsigned long long ev;
            { ev = packdup(e.x); ulonglong2 qa = qt[0], qb = qt[1];
              accA[0] = fma2(ev, qa.x, accA[0]); accA[1] = fma2(ev, qa.y, accA[1]);
              accA[2] = fma2(ev, qb.x, accA[2]); accA[3] = fma2(ev, qb.y, accA[3]); }
            { ev = packdup(e.y); ulonglong2 qa = qt[2], qb = qt[3];
              accB[0] = fma2(ev, qa.x, accB[0]); accB[1] = fma2(ev, qa.y, accB[1]);
              accB[2] = fma2(ev, qb.x, accB[2]); accB[3] = fma2(ev, qb.y, accB[3]); }
            { ev = packdup(e.z); ulonglong2 qa = qt[4], qb = qt[5];
              accA[0] = fma2(ev, qa.x, accA[0]); accA[1] = fma2(ev, qa.y, accA[1]);
              accA[2] = fma2(ev, qb.x, accA[2]); accA[3] = fma2(ev, qb.y, accA[3]); }
            { ev = packdup(e.w); ulonglong2 qa = qt[6], qb = qt[7];
              accB[0] = fma2(ev, qa.x, accB[0]); accB[1] = fma2(ev, qa.y, accB[1]);
              accB[2] = fma2(ev, qb.x, accB[2]); accB[3] = fma2(ev, qb.y, accB[3]); }
        }
        float2 p0 = unpack2(add2(accA[0], accB[0]));
        float2 p1 = unpack2(add2(accA[1], accB[1]));
        float2 p2 = unpack2(add2(accA[2], accB[2]));
        float2 p3 = unpack2(add2(accA[3], accB[3]));
        float vals[8] = {p0.x, p0.y, p1.x, p1.y, p2.x, p2.y, p3.x, p3.y};
        bool m = mkB[n] != 0;
        #pragma unroll
        for (int h = 0; h < HH; h++) s_compat[h * NN + n] = m ? NEGV : vals[h];
    }
    __syncthreads();

    // ---------------- Phase 1b: per-head softmax (one warp per head) -------
    {
        float* row = s_compat + warp * NN;
        float mx = -3.4e38f;
        for (int n = lane; n < NN; n += 32) mx = fmaxf(mx, row[n]);
        #pragma unroll
        for (int o = 16; o > 0; o >>= 1) mx = fmaxf(mx, __shfl_xor_sync(0xffffffffu, mx, o));
        float sm = 0.f;
        for (int n = lane; n < NN; n += 32) {
            float ev = expf(row[n] - mx);
            row[n] = ev; sm += ev;
        }
        #pragma unroll
        for (int o = 16; o > 0; o >>= 1) sm += __shfl_xor_sync(0xffffffffu, sm, o);
        float inv = 1.0f / sm;
        for (int n = lane; n < NN; n += 32) row[n] *= inv;
    }
    __syncthreads();

    // ---------------- Phase 2: ebar[h] = sum_n attn[h][n] * emb[n] ---------
    {
        const float* at = s_compat + warp * NN;
        unsigned long long a0x = 0, a0y = 0, a1x = 0, a1y = 0;
        unsigned long long a2x = 0, a2y = 0, a3x = 0, a3y = 0;
        for (int n = 0; n < NN; n += 4) {
            unsigned long long p0 = packdup(at[n]);
            unsigned long long p1 = packdup(at[n + 1]);
            unsigned long long p2 = packdup(at[n + 2]);
            unsigned long long p3 = packdup(at[n + 3]);
            ulonglong2 e0 = ((const ulonglong2*)(embB + (size_t)n * DD))[lane];
            ulonglong2 e1 = ((const ulonglong2*)(embB + (size_t)(n + 1) * DD))[lane];
            ulonglong2 e2 = ((const ulonglong2*)(embB + (size_t)(n + 2) * DD))[lane];
            ulonglong2 e3 = ((const ulonglong2*)(embB + (size_t)(n + 3) * DD))[lane];
            a0x = fma2(p0, e0.x, a0x); a0y = fma2(p0, e0.y, a0y);
            a1x = fma2(p1, e1.x, a1x); a1y = fma2(p1, e1.y, a1y);
            a2x = fma2(p2, e2.x, a2x); a2y = fma2(p2, e2.y, a2y);
            a3x = fma2(p3, e3.x, a3x); a3y = fma2(p3, e3.y, a3y);
        }
        float2 fx = unpack2(add2(add2(a0x, a1x), add2(a2x, a3x)));
        float2 fy = unpack2(add2(add2(a0y, a1y), add2(a2y, a3y)));
        ((float4*)(s_ebar + warp * DD))[lane] = make_float4(fx.x, fx.y, fy.x, fy.y);
    }
    __syncthreads();

    // ------------- Phase 2b: heads -> glimpse -> gtilde (small matvecs) ----
    if (t < DD) {   // heads[h*16+k] = ebar_h . W_V[:, h*16+k]
        int h = t >> 4;
        const float* eb = s_ebar + h * DD;
        float acc = 0.f;
        for (int d = 0; d < DD; d++) acc += eb[d] * Wn[d * 384 + 128 + t];
        s_heads[t] = acc;
    }
    __syncthreads();
    if (t < DD) {   // glimpse = heads @ W_out
        float acc = 0.f;
        for (int i = 0; i < DD; i++) acc += s_heads[i] * Wo[i * DD + t];
        s_gl[t] = acc;
    }
    __syncthreads();
    if (t < DD) {   // gtilde[d] = W_L[d,:] . glimpse / sqrt(D)
        const float* w = Wn + t * 384 + 256;
        float acc = 0.f;
        for (int j = 0; j < DD; j++) acc += w[j] * s_gl[j];
        s_gt[t] = acc * 0.08838834764831845f;   // 1/sqrt(128)
    }
    __syncthreads();

    // ---------------- Phase 3: logits + log_softmax ------------------------
    float lmax = -3.4e38f;
    for (int n = t; n < NN; n += 256) {
        const ulonglong2* e2p = (const ulonglong2*)(embB + (size_t)n * DD);
        const ulonglong2* g2p = (const ulonglong2*)s_gt;
        unsigned long long a0 = 0, a1 = 0, b0 = 0, b1 = 0;
        #pragma unroll 8
        for (int j = 0; j < 32; j += 2) {
            ulonglong2 e = e2p[j], g = g2p[j];
            a0 = fma2(e.x, g.x, a0); a1 = fma2(e.y, g.y, a1);
            ulonglong2 e1 = e2p[j + 1], g1 = g2p[j + 1];
            b0 = fma2(e1.x, g1.x, b0); b1 = fma2(e1.y, g1.y, b1);
        }
        float2 r = unpack2(add2(add2(a0, b0), add2(a1, b1)));
        float v = tanhf(r.x + r.y) * 10.0f;
        if (mkB[n] != 0) v = NEGV;
        s_compat[n] = v;
        lmax = fmaxf(lmax, v);
    }
    #pragma unroll
    for (int o = 16; o > 0; o >>= 1) lmax = fmaxf(lmax, __shfl_xor_sync(0xffffffffu, lmax, o));
    if (lane == 0) s_red[warp] = lmax;
    __syncthreads();
    float bmax = s_red[0];
    #pragma unroll
    for (int w = 1; w < 8; w++) bmax = fmaxf(bmax, s_red[w]);
    float ls = 0.f;
    for (int n = t; n < NN; n += 256) ls += expf(s_compat[n] - bmax);
    #pragma unroll
    for (int o = 16; o > 0; o >>= 1) ls += __shfl_xor_sync(0xffffffffu, ls, o);
    if (lane == 0) s_red[8 + warp] = ls;
    __syncthreads();
    float tot = s_red[8];
    #pragma unroll
    for (int w = 1; w < 8; w++) tot += s_red[8 + w];
    float logZ = bmax + logf(tot);
    float* outB = out + (size_t)b * NN;
    for (int n = t; n < NN; n += 256) outB[n] = s_compat[n] - logZ;
}

extern "C" void kernel_launch(void* const* d_in, const int* in_sizes, int n_in,
                              void* d_out, int out_size) {
    const float* emb = (const float*)d_in[0];
    const float* Wn  = (const float*)d_in[1];
    const float* Wf  = (const float*)d_in[2];
    const float* Ws  = (const float*)d_in[3];
    const float* Wo  = (const float*)d_in[4];
    const int* fidx  = (const int*)d_in[5];
    const int* lidx  = (const int*)d_in[6];
    const int* mask  = (const int*)d_in[7];
    float* out = (float*)d_out;
    attn_fused_kernel<<<BB, 256>>>(emb, Wn, Wf, Ws, Wo, fidx, lidx, mask, out);
}